// round 11
// baseline (speedup 1.0000x reference)
#include <cuda_runtime.h>
#include <math.h>

#define DIM 200
#define RED 8
#define JC 20            // columns per chunk
#define NCH 10           // chunks per sign (10*20 = 200)
#define TSTRIDE 20       // smem row stride in floats (80B rows, 16B aligned)
#define TILEF (DIM * TSTRIDE)   // floats per tile buffer (4000)
#define NJP (DIM / 2)    // 100 j-pairs

typedef unsigned long long ull;

// ---- persistent device scratch (no allocations allowed) ----
__device__ float  g_kp[2][DIM * RED];       // relu(kernel_p), relu(kernel_n)
__device__ float2 g_kp04[2][NJP * 4];       // [s][jp*4+m]   = (kp[2jp][m], kp[2jp+1][m]) m=0..3
__device__ float2 g_kp47[2][NJP * 4];       // [s][jp*4+m-4] = (kp[2jp][m], kp[2jp+1][m]) m=4..7
__device__ float  g_Wc[2 * 128];            // lin2_w @ lin1_w  (2 x 128)
__device__ float  g_bc[2];                  // lin2_w @ lin1_b + lin2_b

// constants: kp row-major (fold step) + kp pairs m4..7 (mainloop, constant port)
__constant__ float  c_kp[2][DIM * RED];
__constant__ float2 c_kp47[2][NJP * 4];

// ---------------- cp.async helpers ----------------
__device__ __forceinline__ void cp_async16(void* smem_dst, const void* gmem_src) {
    unsigned saddr = (unsigned)__cvta_generic_to_shared(smem_dst);
    asm volatile("cp.async.cg.shared.global [%0], [%1], 16;\n"
                 :: "r"(saddr), "l"(gmem_src) : "memory");
}
__device__ __forceinline__ void cp_commit() {
    asm volatile("cp.async.commit_group;\n" ::: "memory");
}
template <int N>
__device__ __forceinline__ void cp_wait() {
    asm volatile("cp.async.wait_group %0;\n" :: "n"(N) : "memory");
}

// packed dual-FMA: acc.(lo,hi) += a.(lo,hi) * b.(lo,hi)
__device__ __forceinline__ void ffma2(ull& acc, ull a, ull b) {
    asm("fma.rn.f32x2 %0, %1, %2, %0;" : "+l"(acc) : "l"(a), "l"(b));
}
__device__ __forceinline__ float ull_sum(ull v) {
    return __int_as_float((int)(v & 0xffffffffull)) + __int_as_float((int)(v >> 32));
}

// =====================================================================
// Setup: relu(kernels), pair layouts, fused linear, static loss
// =====================================================================
__global__ void gnn_setup_kernel(
    const float* __restrict__ kp_p, const float* __restrict__ kp_n,
    const float* __restrict__ Wp1, const float* __restrict__ Wp2, const float* __restrict__ Wp3,
    const float* __restrict__ Wn1, const float* __restrict__ Wn2, const float* __restrict__ Wn3,
    const float* __restrict__ lin1_w, const float* __restrict__ lin1_b,
    const float* __restrict__ lin2_w, const float* __restrict__ lin2_b,
    float* __restrict__ out, int loss_idx, int write_loss)
{
    __shared__ float gram_s[128];
    __shared__ float loss_s;
    int tid = threadIdx.x;           // launched with 256 threads exactly
    if (tid == 0) loss_s = 0.f;
    float lp = 0.f;

    // relu kernels + neg penalty + L1(|relu|) penalty
    for (int i = tid; i < DIM * RED; i += 256) {
        float a = kp_p[i], b = kp_n[i];
        float ra = fmaxf(a, 0.f), rb = fmaxf(b, 0.f);
        g_kp[0][i] = ra;
        g_kp[1][i] = rb;
        lp += 0.1f * fmaxf(1e-6f - a, 0.f) + 0.1f * fmaxf(1e-6f - b, 0.f);
        lp += 0.05f * (ra + rb);
    }
    // gcn neg-penalties on the six 8x8 W's
    if (tid < 64) {
        lp += 0.2f * (fmaxf(1e-6f - Wp1[tid], 0.f) + fmaxf(1e-6f - Wp2[tid], 0.f) +
                      fmaxf(1e-6f - Wp3[tid], 0.f) + fmaxf(1e-6f - Wn1[tid], 0.f) +
                      fmaxf(1e-6f - Wn2[tid], 0.f) + fmaxf(1e-6f - Wn3[tid], 0.f));
    }
    __syncthreads();   // g_kp visible to block

    // pair-interleaved layouts: m0..3 (smem path) and m4..7 (constant path)
    for (int i = tid; i < 2 * NJP * 4; i += 256) {
        int s  = i / (NJP * 4);
        int r  = i - s * (NJP * 4);
        int jp = r >> 2, m = r & 3;
        g_kp04[s][r] = make_float2(g_kp[s][(2 * jp) * 8 + m],
                                   g_kp[s][(2 * jp + 1) * 8 + m]);
        g_kp47[s][r] = make_float2(g_kp[s][(2 * jp) * 8 + m + 4],
                                   g_kp[s][(2 * jp + 1) * 8 + m + 4]);
    }

    // gram = kp^T kp, ortho penalty on off-diagonals
    if (tid < 128) {
        int side = tid >> 6, a = (tid >> 3) & 7, b2 = tid & 7;
        const float* kp = g_kp[side];
        float s = 0.f;
        for (int n = 0; n < DIM; n++) s += kp[n * 8 + a] * kp[n * 8 + b2];
        gram_s[tid] = s;
        if (a != b2) lp += 0.2f * s * s;
    }
    __syncthreads();

    // variance of gram diagonal, ddof=1 (0.3 for p-side, 0.5 for n-side)
    if (tid < 2) {
        const float* g = gram_s + tid * 64;
        float mean = 0.f;
        for (int a = 0; a < 8; a++) mean += g[a * 9];
        mean *= 0.125f;
        float v = 0.f;
        for (int a = 0; a < 8; a++) { float d = g[a * 9] - mean; v += d * d; }
        v *= (1.0f / 7.0f);
        lp += (tid ? 0.5f : 0.3f) * v;
    }

    // fused linear:  Wc[c][f] = sum_h lin2_w[c][h] * lin1_w[h][f]
    {
        int c = tid >> 7, f = tid & 127;
        float s = 0.f;
        #pragma unroll
        for (int h = 0; h < 16; h++) s += lin2_w[c * 16 + h] * lin1_w[h * 128 + f];
        g_Wc[tid] = s;
    }
    if (tid < 2) {
        float s = lin2_b[tid];
        #pragma unroll
        for (int h = 0; h < 16; h++) s += lin2_w[tid * 16 + h] * lin1_b[h];
        g_bc[tid] = s;
    }

    atomicAdd(&loss_s, lp);
    __syncthreads();
    if (tid == 0 && write_loss) out[loss_idx] = loss_s;
}

// =====================================================================
// Main: per-batch fused  reduced = kp^T A kp -> 3x GCN -> fused linear
// R6 frame: cp.async double buffer + FFMA2 compute, kp split smem/const.
// R11 deltas: chunk-invariant staging offsets (no per-chunk div/mod),
// dedicated AF/part, cross-sign 1-ahead pipeline (no DRAM drain at the
// sign boundary).
// =====================================================================
__global__ void __launch_bounds__(256, 5) gnn_main_kernel(
    const float* __restrict__ A,
    const float* __restrict__ Wp1, const float* __restrict__ Wp2, const float* __restrict__ Wp3,
    const float* __restrict__ Wn1, const float* __restrict__ Wn2, const float* __restrict__ Wn3,
    float* __restrict__ out)
{
    extern __shared__ float sm[];
    float* tile = sm;                    // 2 * TILEF = 8000 floats (double buffer)
    float* kpp  = tile + 2 * TILEF;      // 800 floats: kp pairs m0..3 for current sign
    float* AF   = kpp + 2 * NJP * 4;     // 1600 floats (dedicated)
    float* part = AF + DIM * RED;        // 256 floats (dedicated)
    float* W_s  = part + 256;            // 192 (3 layers x 64)
    float* Rm   = W_s + 192;             // 64
    float* Msm  = Rm + 64;               // 64
    float* Ysm  = Msm + 64;              // 64
    float* Xsm  = Ysm + 64;              // 64
    float* feat = Xsm + 64;              // 128

    const int b = blockIdx.x;
    const int tid = threadIdx.x;
    const float* Abase = A + (size_t)b * 2 * (DIM * DIM);

    // ---- chunk-invariant staging map: idx_k = tid + 256k -> (row, c4) ----
    // copies 1000 float4 per chunk; k=3 predicated (tid < 232)
    int   sOff[4];            // smem float offset within a tile buffer
    int   gOff[4];            // global float4 offset within sign-matrix at col 0
    #pragma unroll
    for (int k = 0; k < 4; k++) {
        int idx = tid + 256 * k;
        int r   = idx / 5;
        int c4  = idx - r * 5;
        sOff[k] = r * TSTRIDE + c4 * 4;
        gOff[k] = r * (DIM / 4) + c4;
    }
    const bool act3 = (tid < 1000 - 768);

    // stage global chunk g_ (0..19): sign g_/10, col (g_%10)*20, buffer g_&1
    #define ISSUE_CHUNK(g_)                                                        \
        {                                                                          \
            int gg = (g_);                                                         \
            const float4* src = (const float4*)(Abase + (gg / NCH) * (DIM * DIM))  \
                              + (gg % NCH) * (JC / 4);                             \
            float* dstb = tile + (gg & 1) * TILEF;                                 \
            cp_async16(dstb + sOff[0], src + gOff[0]);                             \
            cp_async16(dstb + sOff[1], src + gOff[1]);                             \
            cp_async16(dstb + sOff[2], src + gOff[2]);                             \
            if (act3) cp_async16(dstb + sOff[3], src + gOff[3]);                   \
            cp_commit();                                                           \
        }

    // prologue: stage chunk 0 only (loop uniformly stages g+1)
    ISSUE_CHUNK(0)

    for (int s = 0; s < 2; s++) {
        // stage kp pairs m0..3 (400 float2 = 200 float4) and the three W's
        if (tid < 200) ((float4*)kpp)[tid] = ((const float4*)g_kp04[s])[tid];
        if (tid < 192) {
            const float* w;
            if (s == 0) w = (tid < 64) ? Wp1 : ((tid < 128) ? Wp2 : Wp3);
            else        w = (tid < 64) ? Wn1 : ((tid < 128) ? Wn2 : Wn3);
            W_s[tid] = w[tid & 63];
        }
        __syncthreads();   // kpp/W_s visible (also: prev compute done)

        const ulonglong2* k03 = (const ulonglong2*)kpp;
        const ulonglong2* k47 = (const ulonglong2*)c_kp47[s];

        ull acc[8];   // acc[m] = (sum over even j, sum over odd j)
        #pragma unroll
        for (int m = 0; m < 8; m++) acc[m] = 0ull;

        for (int c = 0; c < NCH; c++) {
            const int g = s * NCH + c;
            // stage g+1 (other buffer; crosses the sign boundary at g=9)
            if (g + 1 < 2 * NCH) {
                ISSUE_CHUNK(g + 1)
                cp_wait<1>();   // chunk g complete (g+1 in flight)
            } else {
                cp_wait<0>();
            }
            __syncthreads();

            // ---- row tid:  AF += adj[tid, c*20:+20] @ kp  (FFMA2, split ports) ----
            if (tid < DIM) {
                const double2* t2 =
                    (const double2*)(tile + (g & 1) * TILEF + tid * TSTRIDE);
                #pragma unroll
                for (int q = 0; q < JC / 4; q++) {
                    double2 a2 = t2[q];
                    ull p0 = __double_as_longlong(a2.x);   // (A[4q],   A[4q+1])
                    ull p1 = __double_as_longlong(a2.y);   // (A[4q+2], A[4q+3])
                    int jp = 10 * c + 2 * q;
                    ulonglong2 kA = k03[jp * 2];           // m0,m1 @ jp
                    ulonglong2 kB = k03[jp * 2 + 1];       // m2,m3 @ jp
                    ulonglong2 kC = k03[jp * 2 + 2];       // m0,m1 @ jp+1
                    ulonglong2 kD = k03[jp * 2 + 3];       // m2,m3 @ jp+1
                    ffma2(acc[0], p0, kA.x); ffma2(acc[1], p0, kA.y);
                    ffma2(acc[2], p0, kB.x); ffma2(acc[3], p0, kB.y);
                    ffma2(acc[0], p1, kC.x); ffma2(acc[1], p1, kC.y);
                    ffma2(acc[2], p1, kD.x); ffma2(acc[3], p1, kD.y);
                    ulonglong2 kE = k47[jp * 2];           // m4,m5 @ jp
                    ulonglong2 kF = k47[jp * 2 + 1];       // m6,m7 @ jp
                    ulonglong2 kG = k47[jp * 2 + 2];       // m4,m5 @ jp+1
                    ulonglong2 kH = k47[jp * 2 + 3];       // m6,m7 @ jp+1
                    ffma2(acc[4], p0, kE.x); ffma2(acc[5], p0, kE.y);
                    ffma2(acc[6], p0, kF.x); ffma2(acc[7], p0, kF.y);
                    ffma2(acc[4], p1, kG.x); ffma2(acc[5], p1, kG.y);
                    ffma2(acc[6], p1, kH.x); ffma2(acc[7], p1, kH.y);
                }
            }
            __syncthreads();    // buffer (g&1) free for refill at iter c+1
        }

        // ---- write AF (dedicated; sign-1 chunk0 already in flight) ----
        if (tid < DIM) {
            #pragma unroll
            for (int m = 0; m < 8; m++) AF[tid * 8 + m] = ull_sum(acc[m]);
        }
        __syncthreads();

        // ---- fold: reduced[a,m] = sum_n kp[n,a] * AF[n,m] ----
        {
            int g2 = tid >> 6, am = tid & 63, a = am >> 3, m = am & 7;
            const float* kpf = c_kp[s];
            float sacc = 0.f;
            int n0 = g2 * 50;
            #pragma unroll 5
            for (int n = n0; n < n0 + 50; n++)
                sacc = fmaf(kpf[n * 8 + a], AF[n * 8 + m], sacc);
            part[tid] = sacc;
        }
        __syncthreads();
        if (tid < 64) Rm[tid] = part[tid] + part[tid + 64] + part[tid + 128] + part[tid + 192];
        __syncthreads();

        // ---- GCN chain on 8x8 (thread (i,j) per element) ----
        const int i = tid >> 3, j = tid & 7;
        for (int l = 0; l < 3; l++) {
            if (tid < 64) {
                float mv;
                if (l == 0) mv = W_s[tid];                   // x=None -> M = W
                else {
                    mv = 0.f;
                    #pragma unroll
                    for (int k = 0; k < 8; k++)
                        mv = fmaf(Xsm[i * 8 + k], W_s[l * 64 + k * 8 + j], mv);
                }
                Msm[tid] = mv;
            }
            __syncthreads();
            if (tid < 64) {
                float t = 0.f;
                #pragma unroll
                for (int k = 0; k < 8; k++)
                    t = fmaf(Rm[i * 8 + k], Msm[k * 8 + j], t);
                float y = ((i == j) ? 1.0f : 0.0f) + 0.85f * t;
                Ysm[tid] = fmaxf(y, 0.f);
            }
            __syncthreads();
            if (tid < 64) {
                float cs = 0.f;
                #pragma unroll
                for (int r = 0; r < 8; r++) cs += Ysm[r * 8 + j];
                float cm = cs * 0.125f + 1e-6f;
                float z = Ysm[tid] / cm;                     // z >= 0
                Xsm[tid] = z + log1pf(__expf(-z));           // softplus, stable
            }
            __syncthreads();
        }
        if (tid < 64) feat[i * 16 + s * 8 + j] = Xsm[tid];   // concat layout (B,8,16)
        __syncthreads();
    }

    // ---- fused 128 -> 2 linear ----
    if (tid < 2) {
        float acc2 = g_bc[tid];
        const float* w = g_Wc + tid * 128;
        #pragma unroll 8
        for (int f = 0; f < 128; f++) acc2 = fmaf(w[f], feat[f], acc2);
        out[(size_t)b * 2 + tid] = acc2;
    }
    #undef ISSUE_CHUNK
}

// =====================================================================
extern "C" void kernel_launch(void* const* d_in, const int* in_sizes, int n_in,
                              void* d_out, int out_size)
{
    const float* A        = (const float*)d_in[0];
    const float* kernel_p = (const float*)d_in[1];
    const float* kernel_n = (const float*)d_in[2];
    const float* Wp1      = (const float*)d_in[3];
    const float* Wp2      = (const float*)d_in[4];
    const float* Wp3      = (const float*)d_in[5];
    const float* Wn1      = (const float*)d_in[6];
    const float* Wn2      = (const float*)d_in[7];
    const float* Wn3      = (const float*)d_in[8];
    const float* lin1_w   = (const float*)d_in[9];
    const float* lin1_b   = (const float*)d_in[10];
    const float* lin2_w   = (const float*)d_in[11];
    const float* lin2_b   = (const float*)d_in[12];
    float* out = (float*)d_out;

    const int B = in_sizes[0] / (2 * DIM * DIM);   // 4096
    const int loss_idx = B * 2;
    const int write_loss = (out_size > loss_idx) ? 1 : 0;

    gnn_setup_kernel<<<1, 256>>>(kernel_p, kernel_n, Wp1, Wp2, Wp3, Wn1, Wn2, Wn3,
                                 lin1_w, lin1_b, lin2_w, lin2_b,
                                 out, loss_idx, write_loss);

    // relu'd kernels -> constant memory (async D2D, graph-capturable)
    void* p = nullptr;
    cudaGetSymbolAddress(&p, g_kp);
    cudaMemcpyToSymbolAsync(c_kp, p, sizeof(float) * 2 * DIM * RED, 0,
                            cudaMemcpyDeviceToDevice, 0);
    cudaGetSymbolAddress(&p, g_kp47);
    cudaMemcpyToSymbolAsync(c_kp47, p, sizeof(float2) * 2 * NJP * 4, 0,
                            cudaMemcpyDeviceToDevice, 0);

    const int smem_floats = 2 * TILEF + 2 * NJP * 4 + DIM * RED + 256
                          + 192 + 64 + 64 + 64 + 64 + 128;
    gnn_main_kernel<<<B, 256, smem_floats * sizeof(float)>>>(
        A, Wp1, Wp2, Wp3, Wn1, Wn2, Wn3, out);
}

// round 12
// speedup vs baseline: 1.4846x; 1.4846x over previous
#include <cuda_runtime.h>
#include <cuda.h>
#include <math.h>

#define DIM 200
#define RED 8
#define JC 20            // columns per chunk
#define NCH 10           // chunks per sign (10*20 = 200)
#define TSTRIDE 20       // smem row stride in floats (80B rows; TMA box packs to this)
#define TILEF (DIM * TSTRIDE)   // floats per tile buffer (4000)
#define TILEB (TILEF * 4)       // bytes per tile buffer (16000)
#define NJP (DIM / 2)    // 100 j-pairs

typedef unsigned long long ull;

// ---- persistent device scratch (no allocations allowed) ----
__device__ float  g_kp[2][DIM * RED];       // relu(kernel_p), relu(kernel_n)
__device__ float2 g_kp04[2][NJP * 4];       // [s][jp*4+m]   = (kp[2jp][m], kp[2jp+1][m]) m=0..3
__device__ float2 g_kp47[2][NJP * 4];       // [s][jp*4+m-4] = (kp[2jp][m], kp[2jp+1][m]) m=4..7
__device__ float  g_Wc[2 * 128];            // lin2_w @ lin1_w  (2 x 128)
__device__ float  g_bc[2];                  // lin2_w @ lin1_b + lin2_b

// constants: kp row-major (fold step) + kp pairs m4..7 (mainloop, constant port)
__constant__ float  c_kp[2][DIM * RED];
__constant__ float2 c_kp47[2][NJP * 4];

// ---------------- PTX helpers ----------------
__device__ __forceinline__ unsigned smem_u32(const void* p) {
    return (unsigned)__cvta_generic_to_shared(p);
}
__device__ __forceinline__ void mbar_init(unsigned mbar, unsigned count) {
    asm volatile("mbarrier.init.shared.b64 [%0], %1;" :: "r"(mbar), "r"(count) : "memory");
}
__device__ __forceinline__ void mbar_arrive_tx(unsigned mbar, unsigned tx) {
    asm volatile("mbarrier.arrive.expect_tx.shared::cta.b64 _, [%0], %1;"
                 :: "r"(mbar), "r"(tx) : "memory");
}
__device__ __forceinline__ void mbar_wait_parity(unsigned mbar, unsigned phase) {
    asm volatile(
        "{\n\t"
        ".reg .pred P;\n\t"
        "WAITLOOP_%=:\n\t"
        "mbarrier.try_wait.parity.acquire.cta.shared::cta.b64 P, [%0], %1, 0x989680;\n\t"
        "@!P bra WAITLOOP_%=;\n\t"
        "}" :: "r"(mbar), "r"(phase) : "memory");
}
// 2D TMA load: global tile -> shared::cta, completion via mbarrier complete_tx
__device__ __forceinline__ void tma_load_2d_cta(unsigned dst, const CUtensorMap* map,
                                                int x, int y, unsigned mbar) {
    asm volatile("cp.async.bulk.tensor.2d.shared::cta.global.tile.mbarrier::complete_tx::bytes "
                 "[%0], [%1, {%2, %3}], [%4];"
                 :: "r"(dst), "l"(map), "r"(x), "r"(y), "r"(mbar) : "memory");
}
// packed dual-FMA: acc.(lo,hi) += a.(lo,hi) * b.(lo,hi)
__device__ __forceinline__ void ffma2(ull& acc, ull a, ull b) {
    asm("fma.rn.f32x2 %0, %1, %2, %0;" : "+l"(acc) : "l"(a), "l"(b));
}
__device__ __forceinline__ float ull_sum(ull v) {
    return __int_as_float((int)(v & 0xffffffffull)) + __int_as_float((int)(v >> 32));
}

// =====================================================================
// Setup: relu(kernels), pair layouts, fused linear, static loss
// =====================================================================
__global__ void gnn_setup_kernel(
    const float* __restrict__ kp_p, const float* __restrict__ kp_n,
    const float* __restrict__ Wp1, const float* __restrict__ Wp2, const float* __restrict__ Wp3,
    const float* __restrict__ Wn1, const float* __restrict__ Wn2, const float* __restrict__ Wn3,
    const float* __restrict__ lin1_w, const float* __restrict__ lin1_b,
    const float* __restrict__ lin2_w, const float* __restrict__ lin2_b,
    float* __restrict__ out, int loss_idx, int write_loss)
{
    __shared__ float gram_s[128];
    __shared__ float loss_s;
    int tid = threadIdx.x;           // launched with 256 threads exactly
    if (tid == 0) loss_s = 0.f;
    float lp = 0.f;

    // relu kernels + neg penalty + L1(|relu|) penalty
    for (int i = tid; i < DIM * RED; i += 256) {
        float a = kp_p[i], b = kp_n[i];
        float ra = fmaxf(a, 0.f), rb = fmaxf(b, 0.f);
        g_kp[0][i] = ra;
        g_kp[1][i] = rb;
        lp += 0.1f * fmaxf(1e-6f - a, 0.f) + 0.1f * fmaxf(1e-6f - b, 0.f);
        lp += 0.05f * (ra + rb);
    }
    // gcn neg-penalties on the six 8x8 W's
    if (tid < 64) {
        lp += 0.2f * (fmaxf(1e-6f - Wp1[tid], 0.f) + fmaxf(1e-6f - Wp2[tid], 0.f) +
                      fmaxf(1e-6f - Wp3[tid], 0.f) + fmaxf(1e-6f - Wn1[tid], 0.f) +
                      fmaxf(1e-6f - Wn2[tid], 0.f) + fmaxf(1e-6f - Wn3[tid], 0.f));
    }
    __syncthreads();   // g_kp visible to block

    // pair-interleaved layouts: m0..3 (smem path) and m4..7 (constant path)
    for (int i = tid; i < 2 * NJP * 4; i += 256) {
        int s  = i / (NJP * 4);
        int r  = i - s * (NJP * 4);
        int jp = r >> 2, m = r & 3;
        g_kp04[s][r] = make_float2(g_kp[s][(2 * jp) * 8 + m],
                                   g_kp[s][(2 * jp + 1) * 8 + m]);
        g_kp47[s][r] = make_float2(g_kp[s][(2 * jp) * 8 + m + 4],
                                   g_kp[s][(2 * jp + 1) * 8 + m + 4]);
    }

    // gram = kp^T kp, ortho penalty on off-diagonals
    if (tid < 128) {
        int side = tid >> 6, a = (tid >> 3) & 7, b2 = tid & 7;
        const float* kp = g_kp[side];
        float s = 0.f;
        for (int n = 0; n < DIM; n++) s += kp[n * 8 + a] * kp[n * 8 + b2];
        gram_s[tid] = s;
        if (a != b2) lp += 0.2f * s * s;
    }
    __syncthreads();

    // variance of gram diagonal, ddof=1 (0.3 for p-side, 0.5 for n-side)
    if (tid < 2) {
        const float* g = gram_s + tid * 64;
        float mean = 0.f;
        for (int a = 0; a < 8; a++) mean += g[a * 9];
        mean *= 0.125f;
        float v = 0.f;
        for (int a = 0; a < 8; a++) { float d = g[a * 9] - mean; v += d * d; }
        v *= (1.0f / 7.0f);
        lp += (tid ? 0.5f : 0.3f) * v;
    }

    // fused linear:  Wc[c][f] = sum_h lin2_w[c][h] * lin1_w[h][f]
    {
        int c = tid >> 7, f = tid & 127;
        float s = 0.f;
        #pragma unroll
        for (int h = 0; h < 16; h++) s += lin2_w[c * 16 + h] * lin1_w[h * 128 + f];
        g_Wc[tid] = s;
    }
    if (tid < 2) {
        float s = lin2_b[tid];
        #pragma unroll
        for (int h = 0; h < 16; h++) s += lin2_w[tid * 16 + h] * lin1_b[h];
        g_bc[tid] = s;
    }

    atomicAdd(&loss_s, lp);
    __syncthreads();
    if (tid == 0 && write_loss) out[loss_idx] = loss_s;
}

// =====================================================================
// Main: R6 skeleton verbatim, with the ONE change: staging is a single
// 2D-TMA box load (20 cols x 200 rows = 16KB, packed 80B rows) per chunk
// instead of 1000 LDGSTS. Compute identical to R6 (FFMA2, kp split
// smem/const, conflict-free LDS).
// =====================================================================
__global__ void __launch_bounds__(256, 5) gnn_main_kernel(
    const __grid_constant__ CUtensorMap tmap,
    const float* __restrict__ Wp1, const float* __restrict__ Wp2, const float* __restrict__ Wp3,
    const float* __restrict__ Wn1, const float* __restrict__ Wn2, const float* __restrict__ Wn3,
    float* __restrict__ out)
{
    extern __shared__ __align__(128) float sm[];
    float* tile = sm;                    // 2 * TILEF = 8000 floats (double buffer)
    float* kpp  = tile + 2 * TILEF;      // 800 floats: kp pairs m0..3 for current sign
    float* W_s  = kpp + 2 * NJP * 4;     // 192 (3 layers x 64)
    float* Rm   = W_s + 192;             // 64
    float* Msm  = Rm + 64;               // 64
    float* Ysm  = Msm + 64;              // 64
    float* Xsm  = Ysm + 64;              // 64
    float* feat = Xsm + 64;              // 128
    float* AF   = tile;                  // alias buffer 0 (last chunk lives in buffer 1)
    float* part = tile + TILEF;          // alias buffer 1 (chunk 9 consumed before write)

    __shared__ __align__(8) unsigned long long s_mbar[2];

    const int b = blockIdx.x;
    const int tid = threadIdx.x;
    const unsigned mb0 = smem_u32(&s_mbar[0]);
    const unsigned mb1 = smem_u32(&s_mbar[1]);
    const unsigned tile_s = smem_u32(tile);

    if (tid == 0) { mbar_init(mb0, 1); mbar_init(mb1, 1); }
    __syncthreads();

    // issue chunk c_ of sign s_ into buffer (c_&1): one 2D box load
    #define ISSUE_CHUNK(s_, c_)                                                    \
        {                                                                          \
            unsigned mb = ((c_) & 1) ? mb1 : mb0;                                  \
            mbar_arrive_tx(mb, TILEB);                                             \
            tma_load_2d_cta(tile_s + ((c_) & 1) * TILEB, &tmap,                    \
                            (c_) * JC, (b * 2 + (s_)) * DIM, mb);                  \
        }

    unsigned ph0 = 0, ph1 = 0;

    for (int s = 0; s < 2; s++) {
        // stage kp pairs m0..3 (400 float2 = 200 float4) and the three W's
        if (tid < 200) ((float4*)kpp)[tid] = ((const float4*)g_kp04[s])[tid];
        if (tid < 192) {
            const float* w;
            if (s == 0) w = (tid < 64) ? Wp1 : ((tid < 128) ? Wp2 : Wp3);
            else        w = (tid < 64) ? Wn1 : ((tid < 128) ? Wn2 : Wn3);
            W_s[tid] = w[tid & 63];
        }
        __syncthreads();   // kpp/W_s visible; prev-sign epilogue done -> buffers free

        // per-sign prologue: fill both buffers
        if (tid == 0) { ISSUE_CHUNK(s, 0) ISSUE_CHUNK(s, 1) }

        const ulonglong2* k03 = (const ulonglong2*)kpp;
        const ulonglong2* k47 = (const ulonglong2*)c_kp47[s];

        ull acc[8];   // acc[m] = (sum over even j, sum over odd j)
        #pragma unroll
        for (int m = 0; m < 8; m++) acc[m] = 0ull;

        for (int c = 0; c < NCH; c++) {
            // wait for chunk c data (acquire orders the LDS reads below)
            if (c & 1) { mbar_wait_parity(mb1, ph1); ph1 ^= 1; }
            else       { mbar_wait_parity(mb0, ph0); ph0 ^= 1; }

            // ---- row tid:  AF += adj[tid, c*20:+20] @ kp  (FFMA2, split ports) ----
            if (tid < DIM) {
                const double2* t2 =
                    (const double2*)(tile + (c & 1) * TILEF + tid * TSTRIDE);
                #pragma unroll
                for (int q = 0; q < JC / 4; q++) {
                    double2 a2 = t2[q];
                    ull p0 = __double_as_longlong(a2.x);   // (A[4q],   A[4q+1])
                    ull p1 = __double_as_longlong(a2.y);   // (A[4q+2], A[4q+3])
                    int jp = 10 * c + 2 * q;
                    ulonglong2 kA = k03[jp * 2];           // m0,m1 @ jp
                    ulonglong2 kB = k03[jp * 2 + 1];       // m2,m3 @ jp
                    ulonglong2 kC = k03[jp * 2 + 2];       // m0,m1 @ jp+1
                    ulonglong2 kD = k03[jp * 2 + 3];       // m2,m3 @ jp+1
                    ffma2(acc[0], p0, kA.x); ffma2(acc[1], p0, kA.y);
                    ffma2(acc[2], p0, kB.x); ffma2(acc[3], p0, kB.y);
                    ffma2(acc[0], p1, kC.x); ffma2(acc[1], p1, kC.y);
                    ffma2(acc[2], p1, kD.x); ffma2(acc[3], p1, kD.y);
                    ulonglong2 kE = k47[jp * 2];           // m4,m5 @ jp
                    ulonglong2 kF = k47[jp * 2 + 1];       // m6,m7 @ jp
                    ulonglong2 kG = k47[jp * 2 + 2];       // m4,m5 @ jp+1
                    ulonglong2 kH = k47[jp * 2 + 3];       // m6,m7 @ jp+1
                    ffma2(acc[4], p0, kE.x); ffma2(acc[5], p0, kE.y);
                    ffma2(acc[6], p0, kF.x); ffma2(acc[7], p0, kF.y);
                    ffma2(acc[4], p1, kG.x); ffma2(acc[5], p1, kG.y);
                    ffma2(acc[6], p1, kH.x); ffma2(acc[7], p1, kH.y);
                }
            }
            __syncthreads();   // buffer (c&1) fully consumed -> safe to refill

            // refill the freed buffer with chunk c+2 of this sign
            if (tid == 0 && c + 2 < NCH) ISSUE_CHUNK(s, c + 2)
        }

        // ---- write AF (buffer 0; last chunk data was in buffer 1) ----
        if (tid < DIM) {
            #pragma unroll
            for (int m = 0; m < 8; m++) AF[tid * 8 + m] = ull_sum(acc[m]);
        }
        __syncthreads();

        // ---- fold: reduced[a,m] = sum_n kp[n,a] * AF[n,m] ----
        {
            int g2 = tid >> 6, am = tid & 63, a = am >> 3, m = am & 7;
            const float* kpf = c_kp[s];
            float sacc = 0.f;
            int n0 = g2 * 50;
            #pragma unroll 5
            for (int n = n0; n < n0 + 50; n++)
                sacc = fmaf(kpf[n * 8 + a], AF[n * 8 + m], sacc);
            part[tid] = sacc;
        }
        __syncthreads();
        if (tid < 64) Rm[tid] = part[tid] + part[tid + 64] + part[tid + 128] + part[tid + 192];
        __syncthreads();

        // ---- GCN chain on 8x8 (thread (i,j) per element) ----
        const int i = tid >> 3, j = tid & 7;
        for (int l = 0; l < 3; l++) {
            if (tid < 64) {
                float mv;
                if (l == 0) mv = W_s[tid];                   // x=None -> M = W
                else {
                    mv = 0.f;
                    #pragma unroll
                    for (int k = 0; k < 8; k++)
                        mv = fmaf(Xsm[i * 8 + k], W_s[l * 64 + k * 8 + j], mv);
                }
                Msm[tid] = mv;
            }
            __syncthreads();
            if (tid < 64) {
                float t = 0.f;
                #pragma unroll
                for (int k = 0; k < 8; k++)
                    t = fmaf(Rm[i * 8 + k], Msm[k * 8 + j], t);
                float y = ((i == j) ? 1.0f : 0.0f) + 0.85f * t;
                Ysm[tid] = fmaxf(y, 0.f);
            }
            __syncthreads();
            if (tid < 64) {
                float cs = 0.f;
                #pragma unroll
                for (int r = 0; r < 8; r++) cs += Ysm[r * 8 + j];
                float cm = cs * 0.125f + 1e-6f;
                float z = Ysm[tid] / cm;                     // z >= 0
                Xsm[tid] = z + log1pf(__expf(-z));           // softplus, stable
            }
            __syncthreads();
        }
        if (tid < 64) feat[i * 16 + s * 8 + j] = Xsm[tid];   // concat layout (B,8,16)
        __syncthreads();
    }

    // ---- fused 128 -> 2 linear ----
    if (tid < 2) {
        float acc2 = g_bc[tid];
        const float* w = g_Wc + tid * 128;
        #pragma unroll 8
        for (int f = 0; f < 128; f++) acc2 = fmaf(w[f], feat[f], acc2);
        out[(size_t)b * 2 + tid] = acc2;
    }
    #undef ISSUE_CHUNK
}

// =====================================================================
extern "C" void kernel_launch(void* const* d_in, const int* in_sizes, int n_in,
                              void* d_out, int out_size)
{
    const float* A        = (const float*)d_in[0];
    const float* kernel_p = (const float*)d_in[1];
    const float* kernel_n = (const float*)d_in[2];
    const float* Wp1      = (const float*)d_in[3];
    const float* Wp2      = (const float*)d_in[4];
    const float* Wp3      = (const float*)d_in[5];
    const float* Wn1      = (const float*)d_in[6];
    const float* Wn2      = (const float*)d_in[7];
    const float* Wn3      = (const float*)d_in[8];
    const float* lin1_w   = (const float*)d_in[9];
    const float* lin1_b   = (const float*)d_in[10];
    const float* lin2_w   = (const float*)d_in[11];
    const float* lin2_b   = (const float*)d_in[12];
    float* out = (float*)d_out;

    const int B = in_sizes[0] / (2 * DIM * DIM);   // 4096
    const int loss_idx = B * 2;
    const int write_loss = (out_size > loss_idx) ? 1 : 0;

    gnn_setup_kernel<<<1, 256>>>(kernel_p, kernel_n, Wp1, Wp2, Wp3, Wn1, Wn2, Wn3,
                                 lin1_w, lin1_b, lin2_w, lin2_b,
                                 out, loss_idx, write_loss);

    // relu'd kernels -> constant memory (async D2D, graph-capturable)
    void* p = nullptr;
    cudaGetSymbolAddress(&p, g_kp);
    cudaMemcpyToSymbolAsync(c_kp, p, sizeof(float) * 2 * DIM * RED, 0,
                            cudaMemcpyDeviceToDevice, 0);
    cudaGetSymbolAddress(&p, g_kp47);
    cudaMemcpyToSymbolAsync(c_kp47, p, sizeof(float2) * 2 * NJP * 4, 0,
                            cudaMemcpyDeviceToDevice, 0);

    // ---- encode 2D tensormap for A: [200 cols fp32, B*2*200 rows], box [20, 200]
    // host-side pure encoding via cudart driver-entry-point (no -lcuda, capture-safe)
    CUtensorMap tmap;
    {
        typedef CUresult (*EncFn)(CUtensorMap*, CUtensorMapDataType, cuuint32_t, void*,
                                  const cuuint64_t*, const cuuint64_t*, const cuuint32_t*,
                                  const cuuint32_t*, CUtensorMapInterleave,
                                  CUtensorMapSwizzle, CUtensorMapL2promotion,
                                  CUtensorMapFloatOOBfill);
        void* pfn = nullptr;
        cudaDriverEntryPointQueryResult qr;
#if CUDART_VERSION >= 12050
        cudaGetDriverEntryPointByVersion("cuTensorMapEncodeTiled", &pfn, 12000,
                                         cudaEnableDefault, &qr);
#else
        cudaGetDriverEntryPoint("cuTensorMapEncodeTiled", &pfn, cudaEnableDefault, &qr);
#endif
        EncFn enc = (EncFn)pfn;
        cuuint64_t gdim[2] = {(cuuint64_t)DIM, (cuuint64_t)B * 2 * DIM};
        cuuint64_t gstr[1] = {(cuuint64_t)DIM * sizeof(float)};
        cuuint32_t box[2]  = {JC, DIM};
        cuuint32_t estr[2] = {1, 1};
        enc(&tmap, CU_TENSOR_MAP_DATA_TYPE_FLOAT32, 2, (void*)A,
            gdim, gstr, box, estr,
            CU_TENSOR_MAP_INTERLEAVE_NONE, CU_TENSOR_MAP_SWIZZLE_NONE,
            CU_TENSOR_MAP_L2_PROMOTION_L2_128B, CU_TENSOR_MAP_FLOAT_OOB_FILL_NONE);
    }

    const int smem_floats = 2 * TILEF + 2 * NJP * 4
                          + 192 + 64 + 64 + 64 + 64 + 128;
    gnn_main_kernel<<<B, 256, smem_floats * sizeof(float)>>>(
        tmap, Wp1, Wp2, Wp3, Wn1, Wn2, Wn3, out);
}